// round 5
// baseline (speedup 1.0000x reference)
#include <cuda_runtime.h>
#include <math_constants.h>

#define NPIX  256
#define NFACE 256
#define NVERT 1024

struct FaceData {
    float ax, ay, bx, by, cx, cy;   // 2D vertices
    float Asafe;
    float zi0, zi1, zi2;            // 1/z per vertex
    float u0, u1, u2;               // (uv.x*2-1) * zinv per vertex  (tri9 ch3)
    float v0, v1, v2;               // (uv.y*2-1) * zinv per vertex  (tri9 ch4)
    float bxmin, bxmax, bymin, bymax;
    int   valid;
    int   pad;
};

__device__ FaceData g_faces[NFACE];
__device__ float    g_zinit;

// Detect whether an index buffer is int64 (little-endian: odd 32-bit words are
// zero high-words since all indices < 1024) or int32. Probes 33 odd words,
// in-bounds under BOTH interpretations.
__device__ inline bool probe_i64(const int* p) {
    bool all_zero = true;
    #pragma unroll
    for (int k = 0; k < 33; k++)
        all_zero &= (p[2 * k + 1] == 0);
    return all_zero;
}

__device__ inline int get_idx(const void* p, int k, bool i64) {
    return i64 ? (int)((const long long*)p)[k] : ((const int*)p)[k];
}

// ---------------------------------------------------------------------------
// Kernel 1: per-face precompute + global min-z reduction
// ---------------------------------------------------------------------------
__global__ void precompute_kernel(const float* __restrict__ vertices,
                                  const void* __restrict__ faces,
                                  const float* __restrict__ uv,
                                  const void* __restrict__ uvfaces)
{
    int f = threadIdx.x;

    // --- zinit = min over vertices[:,2] (exact, order-free) ---
    __shared__ float smin[256];
    float zm = CUDART_INF_F;
    for (int v = f; v < NVERT; v += 256)
        zm = fminf(zm, vertices[v * 3 + 2]);
    smin[f] = zm;
    __syncthreads();
    for (int s = 128; s > 0; s >>= 1) {
        if (f < s) smin[f] = fminf(smin[f], smin[f + s]);
        __syncthreads();
    }
    if (f == 0) g_zinit = smin[0];

    bool f_i64  = probe_i64((const int*)faces);
    bool uf_i64 = probe_i64((const int*)uvfaces);

    // --- per-face data ---
    if (f < NFACE) {
        int i0 = get_idx(faces, f * 3 + 0, f_i64);
        int i1 = get_idx(faces, f * 3 + 1, f_i64);
        int i2 = get_idx(faces, f * 3 + 2, f_i64);
        i0 = min(max(i0, 0), NVERT - 1);
        i1 = min(max(i1, 0), NVERT - 1);
        i2 = min(max(i2, 0), NVERT - 1);

        float ax = vertices[i0 * 3 + 0], ay = vertices[i0 * 3 + 1], az = vertices[i0 * 3 + 2];
        float bx = vertices[i1 * 3 + 0], by = vertices[i1 * 3 + 1], bz = vertices[i1 * 3 + 2];
        float cx = vertices[i2 * 3 + 0], cy = vertices[i2 * 3 + 1], cz = vertices[i2 * 3 + 2];

        // area2d == z of cross product, XLA-contracted form:
        //   A = fma(bx-ax, cy-ay, -((by-ay)*(cx-ax)))
        float t2nd = __fmul_rn(__fsub_rn(by, ay), __fsub_rn(cx, ax));
        float A    = __fmaf_rn(__fsub_rn(bx, ax), __fsub_rn(cy, ay), -t2nd);
        int valid = (A >= 1e-9f) ? 1 : 0;
        float Asafe = (fabsf(A) < 1e-9f) ? 1.0f : A;

        float zi0 = __fdiv_rn(1.0f, az);
        float zi1 = __fdiv_rn(1.0f, bz);
        float zi2 = __fdiv_rn(1.0f, cz);

        int t0 = get_idx(uvfaces, f * 3 + 0, uf_i64);
        int t1 = get_idx(uvfaces, f * 3 + 1, uf_i64);
        int t2 = get_idx(uvfaces, f * 3 + 2, uf_i64);
        t0 = min(max(t0, 0), 1023);
        t1 = min(max(t1, 0), 1023);
        t2 = min(max(t2, 0), 1023);

        // uv*2-1: product exact, so fma == mul+sub (either matches the ref)
        float un0 = __fmaf_rn(uv[t0 * 2 + 0], 2.0f, -1.0f);
        float vn0 = __fmaf_rn(uv[t0 * 2 + 1], 2.0f, -1.0f);
        float un1 = __fmaf_rn(uv[t1 * 2 + 0], 2.0f, -1.0f);
        float vn1 = __fmaf_rn(uv[t1 * 2 + 1], 2.0f, -1.0f);
        float un2 = __fmaf_rn(uv[t2 * 2 + 0], 2.0f, -1.0f);
        float vn2 = __fmaf_rn(uv[t2 * 2 + 1], 2.0f, -1.0f);

        FaceData fd;
        fd.ax = ax; fd.ay = ay; fd.bx = bx; fd.by = by; fd.cx = cx; fd.cy = cy;
        fd.Asafe = Asafe;
        fd.zi0 = zi0; fd.zi1 = zi1; fd.zi2 = zi2;
        fd.u0 = __fmul_rn(un0, zi0); fd.v0 = __fmul_rn(vn0, zi0);
        fd.u1 = __fmul_rn(un1, zi1); fd.v1 = __fmul_rn(vn1, zi1);
        fd.u2 = __fmul_rn(un2, zi2); fd.v2 = __fmul_rn(vn2, zi2);
        fd.bxmin = fminf(ax, fminf(bx, cx));
        fd.bxmax = fmaxf(ax, fmaxf(bx, cx));
        fd.bymin = fminf(ay, fminf(by, cy));
        fd.bymax = fmaxf(ay, fmaxf(by, cy));
        fd.valid = valid;
        fd.pad = 0;
        g_faces[f] = fd;
    }
}

// ---------------------------------------------------------------------------
// Kernel 2: rasterize. One 16x16 pixel tile per block (16x16 threads).
// ---------------------------------------------------------------------------
__global__ __launch_bounds__(256)
void raster_kernel(const float* __restrict__ uvmap,
                   float* __restrict__ out)
{
    __shared__ float s_ax[NFACE], s_ay[NFACE], s_bx[NFACE], s_by[NFACE];
    __shared__ float s_cx[NFACE], s_cy[NFACE], s_As[NFACE];
    __shared__ float s_zi0[NFACE], s_zi1[NFACE], s_zi2[NFACE];
    __shared__ float s_u0[NFACE], s_u1[NFACE], s_u2[NFACE];
    __shared__ float s_v0[NFACE], s_v1[NFACE], s_v2[NFACE];
    __shared__ int   s_cnt;
    __shared__ int   s_wcnt[8], s_woff[8];

    const float STEP = 2.0f / 255.0f;   // correctly-rounded f32 linspace step

    int tx = threadIdx.x, ty = threadIdx.y;
    int tid = ty * 16 + tx;
    int j0 = blockIdx.x * 16;           // column range
    int i0 = blockIdx.y * 16;           // row range

    // tile NDC bounds (padded generously; edge-fn fp error band is ~1e-7 rel)
    float pad = 0.02f;
    float tile_xmin = __fadd_rn(__fmul_rn((float)j0,        STEP), -1.0f) - pad;
    float tile_xmax = __fadd_rn(__fmul_rn((float)(j0 + 15), STEP), -1.0f) + pad;
    float tile_ymin = __fadd_rn(__fmul_rn((float)(255 - (i0 + 15)), STEP), -1.0f) - pad;
    float tile_ymax = __fadd_rn(__fmul_rn((float)(255 - i0),        STEP), -1.0f) + pad;

    // ---- ordered compaction of surviving faces (preserves face order so the
    //      argmax first-index tie rule is preserved) ----
    FaceData fd = g_faces[tid];
    bool ok = fd.valid &&
              (fd.bxmax > tile_xmin) && (fd.bxmin < tile_xmax) &&
              (fd.bymax > tile_ymin) && (fd.bymin < tile_ymax);

    unsigned m = __ballot_sync(0xffffffffu, ok);
    int warp = tid >> 5, lane = tid & 31;
    if (lane == 0) s_wcnt[warp] = __popc(m);
    __syncthreads();
    if (tid == 0) {
        int s = 0;
        for (int w = 0; w < 8; w++) { s_woff[w] = s; s += s_wcnt[w]; }
        s_cnt = s;
    }
    __syncthreads();
    if (ok) {
        int p = s_woff[warp] + __popc(m & ((1u << lane) - 1u));
        s_ax[p] = fd.ax; s_ay[p] = fd.ay;
        s_bx[p] = fd.bx; s_by[p] = fd.by;
        s_cx[p] = fd.cx; s_cy[p] = fd.cy;
        s_As[p] = fd.Asafe;
        s_zi0[p] = fd.zi0; s_zi1[p] = fd.zi1; s_zi2[p] = fd.zi2;
        s_u0[p] = fd.u0; s_u1[p] = fd.u1; s_u2[p] = fd.u2;
        s_v0[p] = fd.v0; s_v1[p] = fd.v1; s_v2[p] = fd.v2;
    }
    __syncthreads();
    int cnt = s_cnt;

    // ---- per-pixel raster loop ----
    int j = j0 + tx;
    int i = i0 + ty;
    // pts grid is CONSTANT-FOLDED by XLA (round-per-op evaluator): keep plain
    // mul+add, NOT fma.
    float px = __fadd_rn(__fmul_rn((float)j,         STEP), -1.0f);
    float py = __fadd_rn(__fmul_rn((float)(255 - i), STEP), -1.0f);
    float zinit = g_zinit;

    float best = -CUDART_INF_F;
    int   win = -1;
    float w1w = 0.0f, w2w = 0.0f, w3w = 0.0f;

    for (int k = 0; k < cnt; k++) {
        float ax = s_ax[k], ay = s_ay[k];
        float bx = s_bx[k], by = s_by[k];
        float cx = s_cx[k], cy = s_cy[k];
        // XLA-contracted edge:  fma(px-a.x', c.y'-a.y', -((py-a.y')*(c.x'-a.x')))
        float tAB = __fmul_rn(__fsub_rn(py, by), __fsub_rn(ax, bx));
        float pAB = __fmaf_rn(__fsub_rn(px, bx), __fsub_rn(ay, by), -tAB);
        float tCB = __fmul_rn(__fsub_rn(py, cy), __fsub_rn(bx, cx));
        float pCB = __fmaf_rn(__fsub_rn(px, cx), __fsub_rn(by, cy), -tCB);
        float tCA = __fmul_rn(__fsub_rn(py, ay), __fsub_rn(cx, ax));
        float pCA = __fmaf_rn(__fsub_rn(px, ax), __fsub_rn(cy, ay), -tCA);
        if (pAB > 0.0f && pCB > 0.0f && pCA > 0.0f) {
            float As = s_As[k];
            float w1 = __fdiv_rn(pCB, As);
            float w2 = __fdiv_rn(pCA, As);
            float w3 = __fsub_rn(__fsub_rn(1.0f, w1), w2);
            // contracted: fma(w3, zi2, fma(w1, zi0, w2*zi1))
            float zp = __fmaf_rn(w3, s_zi2[k],
                       __fmaf_rn(w1, s_zi0[k], __fmul_rn(w2, s_zi1[k])));
            float Z = __fdiv_rn(1.0f, zp);
            if (Z >= zinit && Z > best) {   // strict > keeps first-index on ties
                best = Z; win = k;
                w1w = w1; w2w = w2; w3w = w3;
            }
        }
    }

    // ---- shade winner ----
    float r = 0.0f, g = 0.0f, b = 0.0f, h = 0.0f;
    if (win >= 0) {
        // contracted attribute interpolation (same pattern as zp)
        float uP = __fmaf_rn(w3w, s_u2[win],
                   __fmaf_rn(w1w, s_u0[win], __fmul_rn(w2w, s_u1[win])));
        float vP = __fmaf_rn(w3w, s_v2[win],
                   __fmaf_rn(w1w, s_v0[win], __fmul_rn(w2w, s_v1[win])));
        // pts9[...,8] at the winner contracts identically to zp -> Zw == best
        float Zw = best;
        float gx = __fmul_rn(uP, Zw);
        float gy = __fmul_rn(vP, Zw);

        // bilinear_sample, W=H=256; x = fma(gx+1, 256, -1) * 0.5 (contracted)
        float x = __fmul_rn(__fmaf_rn(__fadd_rn(gx, 1.0f), 256.0f, -1.0f), 0.5f);
        float y = __fmul_rn(__fmaf_rn(__fadd_rn(gy, 1.0f), 256.0f, -1.0f), 0.5f);
        float x0 = floorf(x), y0 = floorf(y);
        float x1 = __fadd_rn(x0, 1.0f), y1 = __fadd_rn(y0, 1.0f);
        float wx1 = __fsub_rn(x, x0), wx0 = __fsub_rn(1.0f, wx1);
        float wy1 = __fsub_rn(y, y0), wy0 = __fsub_rn(1.0f, wy1);

        float f00 = (x0 >= 0.0f && x0 <= 255.0f && y0 >= 0.0f && y0 <= 255.0f) ? 1.0f : 0.0f;
        float f10 = (x1 >= 0.0f && x1 <= 255.0f && y0 >= 0.0f && y0 <= 255.0f) ? 1.0f : 0.0f;
        float f01 = (x0 >= 0.0f && x0 <= 255.0f && y1 >= 0.0f && y1 <= 255.0f) ? 1.0f : 0.0f;
        float f11 = (x1 >= 0.0f && x1 <= 255.0f && y1 >= 0.0f && y1 <= 255.0f) ? 1.0f : 0.0f;

        int ix0 = (int)fminf(fmaxf(x0, 0.0f), 255.0f);
        int iy0 = (int)fminf(fmaxf(y0, 0.0f), 255.0f);
        int ix1 = (int)fminf(fmaxf(x1, 0.0f), 255.0f);
        int iy1 = (int)fminf(fmaxf(y1, 0.0f), 255.0f);

        float c00 = __fmul_rn(wx0, wy0);
        float c10 = __fmul_rn(wx1, wy0);
        float c01 = __fmul_rn(wx0, wy1);
        float c11 = __fmul_rn(wx1, wy1);

        int o00 = iy0 * 256 + ix0;
        int o10 = iy0 * 256 + ix1;
        int o01 = iy1 * 256 + ix0;
        int o11 = iy1 * 256 + ix1;

        float rgb[3];
        #pragma unroll
        for (int c = 0; c < 3; c++) {
            const float* im = uvmap + c * 65536;
            float g00 = __fmul_rn(__ldg(im + o00), f00);
            float g10 = __fmul_rn(__ldg(im + o10), f10);
            float g01 = __fmul_rn(__ldg(im + o01), f01);
            float g11 = __fmul_rn(__ldg(im + o11), f11);
            // contracted sum: fma(g11,c11, fma(g01,c01, fma(g00,c00, g10*c10)))
            float acc = __fmaf_rn(g00, c00, __fmul_rn(g10, c10));
            acc = __fmaf_rn(g01, c01, acc);
            acc = __fmaf_rn(g11, c11, acc);
            rgb[c] = acc;
        }
        r = rgb[0]; g = rgb[1]; b = rgb[2]; h = 1.0f;   // hitf==1 -> exact
    }

    int pix = i * 256 + j;
    out[0 * 65536 + pix] = r;
    out[1 * 65536 + pix] = g;
    out[2 * 65536 + pix] = b;
    out[3 * 65536 + pix] = h;
}

// ---------------------------------------------------------------------------
extern "C" void kernel_launch(void* const* d_in, const int* in_sizes, int n_in,
                              void* d_out, int out_size)
{
    const float* vertices = (const float*)d_in[0];      // (1024,3) f32
    const void*  faces    = (const void*)d_in[1];       // (256,3)  int32/int64
    const float* uv       = (const float*)d_in[2];      // (1024,2) f32
    const void*  uvfaces  = (const void*)d_in[3];       // (256,3)  int32/int64
    const float* uvmap    = (const float*)d_in[4];      // (3,256,256) f32
    float*       out      = (float*)d_out;              // (4,256,256) f32

    precompute_kernel<<<1, 256>>>(vertices, faces, uv, uvfaces);
    raster_kernel<<<dim3(16, 16), dim3(16, 16)>>>(uvmap, out);
}

// round 6
// speedup vs baseline: 1.3226x; 1.3226x over previous
#include <cuda_runtime.h>
#include <math_constants.h>

#define NPIX  256
#define NFACE 256
#define NVERT 1024

// Detect whether an index buffer is int64 (little-endian: odd 32-bit words are
// zero high-words since all indices < 1024) or int32. Probes 33 odd words,
// in-bounds under BOTH interpretations.
__device__ __forceinline__ bool probe_i64(const int* p) {
    bool all_zero = true;
    #pragma unroll
    for (int k = 0; k < 33; k++)
        all_zero &= (p[2 * k + 1] == 0);
    return all_zero;
}

__device__ __forceinline__ int get_idx(const void* p, int k, bool i64) {
    return i64 ? (int)((const long long*)p)[k] : ((const int*)p)[k];
}

// ---------------------------------------------------------------------------
// Single fused kernel. One 16x16 pixel tile per block (16x16 threads).
// Each block redundantly computes per-face data (inputs are tiny & L2-hot),
// culls against its tile bbox, compacts survivors into vectorized shared
// arrays, then rasterizes.
// ---------------------------------------------------------------------------
__global__ __launch_bounds__(256)
void render_kernel(const float* __restrict__ vertices,
                   const void*  __restrict__ faces,
                   const float* __restrict__ uv,
                   const void*  __restrict__ uvfaces,
                   const float* __restrict__ uvmap,
                   float*       __restrict__ out)
{
    // hot inner-loop face data, vectorized:
    __shared__ float4 s_f0[NFACE];   // ax, ay, bx, by
    __shared__ float4 s_f1[NFACE];   // cx, cy, Asafe, zi0
    __shared__ float2 s_f2[NFACE];   // zi1, zi2
    // winner-phase only (scalar reads by winner index):
    __shared__ float s_u0[NFACE], s_u1[NFACE], s_u2[NFACE];
    __shared__ float s_v0[NFACE], s_v1[NFACE], s_v2[NFACE];
    __shared__ float s_min[256];
    __shared__ int   s_cnt;
    __shared__ int   s_wcnt[8], s_woff[8];

    const float STEP = 2.0f / 255.0f;   // correctly-rounded f32 linspace step

    int tx = threadIdx.x, ty = threadIdx.y;
    int tid = ty * 16 + tx;
    int j0 = blockIdx.x * 16;           // column range
    int i0 = blockIdx.y * 16;           // row range

    // ---- zinit = min over vertices[:,2] (order-free) ----
    float zm = CUDART_INF_F;
    #pragma unroll
    for (int q = 0; q < 4; q++)
        zm = fminf(zm, vertices[(tid + q * 256) * 3 + 2]);
    s_min[tid] = zm;

    // ---- per-face precompute (this thread owns face `tid`) ----
    bool f_i64  = probe_i64((const int*)faces);
    bool uf_i64 = probe_i64((const int*)uvfaces);

    int i0v = get_idx(faces, tid * 3 + 0, f_i64);
    int i1v = get_idx(faces, tid * 3 + 1, f_i64);
    int i2v = get_idx(faces, tid * 3 + 2, f_i64);
    i0v = min(max(i0v, 0), NVERT - 1);
    i1v = min(max(i1v, 0), NVERT - 1);
    i2v = min(max(i2v, 0), NVERT - 1);

    float ax = vertices[i0v * 3 + 0], ay = vertices[i0v * 3 + 1], az = vertices[i0v * 3 + 2];
    float bx = vertices[i1v * 3 + 0], by = vertices[i1v * 3 + 1], bz = vertices[i1v * 3 + 2];
    float cx = vertices[i2v * 3 + 0], cy = vertices[i2v * 3 + 1], cz = vertices[i2v * 3 + 2];

    // area2d == z of cross product, XLA-contracted:
    //   A = fma(bx-ax, cy-ay, -((by-ay)*(cx-ax)))
    float t2nd = __fmul_rn(__fsub_rn(by, ay), __fsub_rn(cx, ax));
    float A    = __fmaf_rn(__fsub_rn(bx, ax), __fsub_rn(cy, ay), -t2nd);
    bool  valid = (A >= 1e-9f);
    float Asafe = (fabsf(A) < 1e-9f) ? 1.0f : A;

    float zi0 = __fdiv_rn(1.0f, az);
    float zi1 = __fdiv_rn(1.0f, bz);
    float zi2 = __fdiv_rn(1.0f, cz);

    int t0 = get_idx(uvfaces, tid * 3 + 0, uf_i64);
    int t1 = get_idx(uvfaces, tid * 3 + 1, uf_i64);
    int t2 = get_idx(uvfaces, tid * 3 + 2, uf_i64);
    t0 = min(max(t0, 0), 1023);
    t1 = min(max(t1, 0), 1023);
    t2 = min(max(t2, 0), 1023);

    // uv*2-1 (product exact; fma == mul+sub)
    float un0 = __fmaf_rn(uv[t0 * 2 + 0], 2.0f, -1.0f);
    float vn0 = __fmaf_rn(uv[t0 * 2 + 1], 2.0f, -1.0f);
    float un1 = __fmaf_rn(uv[t1 * 2 + 0], 2.0f, -1.0f);
    float vn1 = __fmaf_rn(uv[t1 * 2 + 1], 2.0f, -1.0f);
    float un2 = __fmaf_rn(uv[t2 * 2 + 0], 2.0f, -1.0f);
    float vn2 = __fmaf_rn(uv[t2 * 2 + 1], 2.0f, -1.0f);

    // tile NDC bounds (padded; edge-fn fp error band is ~1e-7 rel)
    float pad = 0.02f;
    float tile_xmin = __fadd_rn(__fmul_rn((float)j0,        STEP), -1.0f) - pad;
    float tile_xmax = __fadd_rn(__fmul_rn((float)(j0 + 15), STEP), -1.0f) + pad;
    float tile_ymin = __fadd_rn(__fmul_rn((float)(255 - (i0 + 15)), STEP), -1.0f) - pad;
    float tile_ymax = __fadd_rn(__fmul_rn((float)(255 - i0),        STEP), -1.0f) + pad;

    float bxmin = fminf(ax, fminf(bx, cx)), bxmax = fmaxf(ax, fmaxf(bx, cx));
    float bymin = fminf(ay, fminf(by, cy)), bymax = fmaxf(ay, fmaxf(by, cy));

    bool ok = valid &&
              (bxmax > tile_xmin) && (bxmin < tile_xmax) &&
              (bymax > tile_ymin) && (bymin < tile_ymax);

    // ---- ordered compaction (preserves face order -> argmax tie rule) ----
    unsigned m = __ballot_sync(0xffffffffu, ok);
    int warp = tid >> 5, lane = tid & 31;
    if (lane == 0) s_wcnt[warp] = __popc(m);
    __syncthreads();
    if (tid == 0) {
        int s = 0;
        #pragma unroll
        for (int w = 0; w < 8; w++) { s_woff[w] = s; s += s_wcnt[w]; }
        s_cnt = s;
        // finish zinit reduction serially-cheap (256 fminf by thread 0? no --
        // do tree below instead)
    }
    __syncthreads();
    // zinit tree reduction (s_min already populated before first sync)
    for (int s = 128; s > 0; s >>= 1) {
        if (tid < s) s_min[tid] = fminf(s_min[tid], s_min[tid + s]);
        __syncthreads();
    }
    float zinit = s_min[0];

    if (ok) {
        int p = s_woff[warp] + __popc(m & ((1u << lane) - 1u));
        s_f0[p] = make_float4(ax, ay, bx, by);
        s_f1[p] = make_float4(cx, cy, Asafe, zi0);
        s_f2[p] = make_float2(zi1, zi2);
        s_u0[p] = __fmul_rn(un0, zi0); s_v0[p] = __fmul_rn(vn0, zi0);
        s_u1[p] = __fmul_rn(un1, zi1); s_v1[p] = __fmul_rn(vn1, zi1);
        s_u2[p] = __fmul_rn(un2, zi2); s_v2[p] = __fmul_rn(vn2, zi2);
    }
    __syncthreads();
    int cnt = s_cnt;

    // ---- per-pixel raster loop ----
    int j = j0 + tx;
    int i = i0 + ty;
    // pts grid is constant-folded by XLA (round-per-op): plain mul+add, NOT fma
    float px = __fadd_rn(__fmul_rn((float)j,         STEP), -1.0f);
    float py = __fadd_rn(__fmul_rn((float)(255 - i), STEP), -1.0f);

    float best = -CUDART_INF_F;
    int   win = -1;
    float w1w = 0.0f, w2w = 0.0f, w3w = 0.0f;

    #pragma unroll 2
    for (int k = 0; k < cnt; k++) {
        float4 f0 = s_f0[k];            // ax ay bx by
        float4 f1 = s_f1[k];            // cx cy As zi0
        // XLA-contracted edge: fma(px-a.x, c.y-a.y, -((py-a.y)*(c.x-a.x)))
        float tAB = __fmul_rn(__fsub_rn(py, f0.w), __fsub_rn(f0.x, f0.z));
        float pAB = __fmaf_rn(__fsub_rn(px, f0.z), __fsub_rn(f0.y, f0.w), -tAB);
        float tCB = __fmul_rn(__fsub_rn(py, f1.y), __fsub_rn(f0.z, f1.x));
        float pCB = __fmaf_rn(__fsub_rn(px, f1.x), __fsub_rn(f0.w, f1.y), -tCB);
        float tCA = __fmul_rn(__fsub_rn(py, f0.y), __fsub_rn(f1.x, f0.x));
        float pCA = __fmaf_rn(__fsub_rn(px, f0.x), __fsub_rn(f1.y, f0.y), -tCA);
        if (pAB > 0.0f && pCB > 0.0f && pCA > 0.0f) {
            float2 f2 = s_f2[k];        // zi1 zi2
            float w1 = __fdiv_rn(pCB, f1.z);
            float w2 = __fdiv_rn(pCA, f1.z);
            float w3 = __fsub_rn(__fsub_rn(1.0f, w1), w2);
            // contracted: fma(w3, zi2, fma(w1, zi0, w2*zi1))
            float zp = __fmaf_rn(w3, f2.y,
                       __fmaf_rn(w1, f1.w, __fmul_rn(w2, f2.x)));
            float Z = __fdiv_rn(1.0f, zp);
            if (Z >= zinit && Z > best) {   // strict > keeps first-index ties
                best = Z; win = k;
                w1w = w1; w2w = w2; w3w = w3;
            }
        }
    }

    // ---- shade winner ----
    float r = 0.0f, g = 0.0f, b = 0.0f, h = 0.0f;
    if (win >= 0) {
        float uP = __fmaf_rn(w3w, s_u2[win],
                   __fmaf_rn(w1w, s_u0[win], __fmul_rn(w2w, s_u1[win])));
        float vP = __fmaf_rn(w3w, s_v2[win],
                   __fmaf_rn(w1w, s_v0[win], __fmul_rn(w2w, s_v1[win])));
        // pts9[...,8] at the winner contracts identically to zp -> Zw == best
        float Zw = best;
        float gx = __fmul_rn(uP, Zw);
        float gy = __fmul_rn(vP, Zw);

        // bilinear_sample, W=H=256; x = fma(gx+1, 256, -1) * 0.5 (contracted)
        float x = __fmul_rn(__fmaf_rn(__fadd_rn(gx, 1.0f), 256.0f, -1.0f), 0.5f);
        float y = __fmul_rn(__fmaf_rn(__fadd_rn(gy, 1.0f), 256.0f, -1.0f), 0.5f);
        float x0 = floorf(x), y0 = floorf(y);
        float x1 = __fadd_rn(x0, 1.0f), y1 = __fadd_rn(y0, 1.0f);
        float wx1 = __fsub_rn(x, x0), wx0 = __fsub_rn(1.0f, wx1);
        float wy1 = __fsub_rn(y, y0), wy0 = __fsub_rn(1.0f, wy1);

        float f00 = (x0 >= 0.0f && x0 <= 255.0f && y0 >= 0.0f && y0 <= 255.0f) ? 1.0f : 0.0f;
        float f10 = (x1 >= 0.0f && x1 <= 255.0f && y0 >= 0.0f && y0 <= 255.0f) ? 1.0f : 0.0f;
        float f01 = (x0 >= 0.0f && x0 <= 255.0f && y1 >= 0.0f && y1 <= 255.0f) ? 1.0f : 0.0f;
        float f11 = (x1 >= 0.0f && x1 <= 255.0f && y1 >= 0.0f && y1 <= 255.0f) ? 1.0f : 0.0f;

        int ix0 = (int)fminf(fmaxf(x0, 0.0f), 255.0f);
        int iy0 = (int)fminf(fmaxf(y0, 0.0f), 255.0f);
        int ix1 = (int)fminf(fmaxf(x1, 0.0f), 255.0f);
        int iy1 = (int)fminf(fmaxf(y1, 0.0f), 255.0f);

        float c00 = __fmul_rn(wx0, wy0);
        float c10 = __fmul_rn(wx1, wy0);
        float c01 = __fmul_rn(wx0, wy1);
        float c11 = __fmul_rn(wx1, wy1);

        int o00 = iy0 * 256 + ix0;
        int o10 = iy0 * 256 + ix1;
        int o01 = iy1 * 256 + ix0;
        int o11 = iy1 * 256 + ix1;

        float rgb[3];
        #pragma unroll
        for (int c = 0; c < 3; c++) {
            const float* im = uvmap + c * 65536;
            float g00 = __fmul_rn(__ldg(im + o00), f00);
            float g10 = __fmul_rn(__ldg(im + o10), f10);
            float g01 = __fmul_rn(__ldg(im + o01), f01);
            float g11 = __fmul_rn(__ldg(im + o11), f11);
            float acc = __fmaf_rn(g00, c00, __fmul_rn(g10, c10));
            acc = __fmaf_rn(g01, c01, acc);
            acc = __fmaf_rn(g11, c11, acc);
            rgb[c] = acc;
        }
        r = rgb[0]; g = rgb[1]; b = rgb[2]; h = 1.0f;   // hitf==1 -> exact
    }

    int pix = i * 256 + j;
    out[0 * 65536 + pix] = r;
    out[1 * 65536 + pix] = g;
    out[2 * 65536 + pix] = b;
    out[3 * 65536 + pix] = h;
}

// ---------------------------------------------------------------------------
extern "C" void kernel_launch(void* const* d_in, const int* in_sizes, int n_in,
                              void* d_out, int out_size)
{
    const float* vertices = (const float*)d_in[0];      // (1024,3) f32
    const void*  faces    = (const void*)d_in[1];       // (256,3)  int32/int64
    const float* uv       = (const float*)d_in[2];      // (1024,2) f32
    const void*  uvfaces  = (const void*)d_in[3];       // (256,3)  int32/int64
    const float* uvmap    = (const float*)d_in[4];      // (3,256,256) f32
    float*       out      = (float*)d_out;              // (4,256,256) f32

    render_kernel<<<dim3(16, 16), dim3(16, 16)>>>(vertices, faces, uv, uvfaces,
                                                  uvmap, out);
}